// round 1
// baseline (speedup 1.0000x reference)
#include <cuda_runtime.h>
#include <cuda_bf16.h>
#include <cstdint>

// Problem constants (fixed by the dataset)
#define BB 512      // batch
#define TT 512      // timesteps
#define II 128      // sensory inputs
#define UU 64       // LTC units
#define OO 15       // outputs
#define NUNF 4      // ode unfolds
#define LTC_EPS 1e-8f

// ---------------- device scratch (allocation-free rule: __device__ globals) ---------
__device__ float4 g_sparam[II * UU];     // sensory per-synapse {a, b, ce, c}
__device__ float4 g_rparam[UU * UU];     // recurrent per-synapse {a, b, ce, c}
__device__ float  g_sKn[UU], g_sKd[UU];  // sensory constant sums
__device__ float  g_cmt[UU], g_numbase[UU], g_denbase[UU];
__device__ float2 g_wns[BB * TT * UU];   // (w_num_s, w_den_s) per (b,t,u)  ~134MB

// ---------------- helpers ------------------------------------------------------------
__device__ __forceinline__ float tanh_fast(float x) {
    float y;
    asm("tanh.approx.f32 %0, %1;" : "=f"(y) : "f"(x));
    return y;
}
__device__ __forceinline__ float softplus_f(float x) {
    return log1pf(expf(x));
}
__device__ __forceinline__ void cp_async16(void* smem, const void* gmem) {
    uint32_t s = (uint32_t)__cvta_generic_to_shared(smem);
    asm volatile("cp.async.cg.shared.global [%0], [%1], 16;" :: "r"(s), "l"(gmem));
}
__device__ __forceinline__ void cp_commit() {
    asm volatile("cp.async.commit_group;");
}
template <int N>
__device__ __forceinline__ void cp_wait() {
    asm volatile("cp.async.wait_group %0;" :: "n"(N));
}

// ---------------- kernel 0: fold parameters ------------------------------------------
// sigmoid(z) = 0.5*tanh(z/2) + 0.5
// sensory arg = 0.5*sigma*(x*iw + ib - mu)   -> a = 0.5*sigma*iw, b = 0.5*sigma*(ib - mu)
// s_act = sp(w) * sigmoid = c + c*th, c = 0.5*sp(w); num term uses ce = c*erev
__global__ void precompute_kernel(
    const float* __restrict__ iw, const float* __restrict__ ib,
    const float* __restrict__ sw, const float* __restrict__ smu,
    const float* __restrict__ ssig, const float* __restrict__ serev,
    const float* __restrict__ w, const float* __restrict__ mu,
    const float* __restrict__ sig, const float* __restrict__ erev,
    const float* __restrict__ gleak, const float* __restrict__ vleak,
    const float* __restrict__ cm)
{
    int u = threadIdx.x;
    if (u >= UU) return;

    float kn = 0.f, kd = 0.f;
    for (int i = 0; i < II; i++) {
        int idx = i * UU + u;
        float c  = 0.5f * softplus_f(sw[idx]);
        float ce = c * serev[idx];
        float a  = 0.5f * ssig[idx] * iw[i];
        float b  = 0.5f * ssig[idx] * (ib[i] - smu[idx]);
        g_sparam[idx] = make_float4(a, b, ce, c);
        kn += ce; kd += c;
    }
    g_sKn[u] = kn;
    g_sKd[u] = kd;

    kn = 0.f; kd = 0.f;
    for (int j = 0; j < UU; j++) {
        int idx = j * UU + u;
        float c  = 0.5f * softplus_f(w[idx]);
        float ce = c * erev[idx];
        float a  = 0.5f * sig[idx];
        float b  = -0.5f * sig[idx] * mu[idx];
        g_rparam[idx] = make_float4(a, b, ce, c);
        kn += ce; kd += c;
    }
    float gp  = softplus_f(gleak[u]);
    float cmt = (float)NUNF * softplus_f(cm[u]);   // sp(cm) / (1/UNFOLDS)
    g_cmt[u]     = cmt;
    g_numbase[u] = gp * vleak[u] + kn;
    g_denbase[u] = cmt + gp + kd + LTC_EPS;
}

// ---------------- kernel 1: sensory synapse sums over all (b,t) ----------------------
// 512 threads: u = tid>>3 (64 units), ig = tid&7 (8 groups of 16 inputs)
// Params register-resident; x rows triple-buffered via cp.async.
#define ROWS_PER_BLOCK 128
__global__ __launch_bounds__(512, 1) void sensory_kernel(const float* __restrict__ x)
{
    __shared__ float xbuf[3][II];
    const int tid = threadIdx.x;
    const int u  = tid >> 3;
    const int ig = tid & 7;

    float4 p[16];
#pragma unroll
    for (int ii = 0; ii < 16; ii++)
        p[ii] = g_sparam[(ig * 16 + ii) * UU + u];
    const float kn = g_sKn[u];
    const float kd = g_sKd[u];

    const size_t base_row = (size_t)blockIdx.x * ROWS_PER_BLOCK;

    // prologue: prefetch rows 0 and 1
    if (tid < 32) {
        cp_async16(&xbuf[0][tid * 4], x + base_row * II + tid * 4);
        cp_commit();
        cp_async16(&xbuf[1][tid * 4], x + (base_row + 1) * II + tid * 4);
        cp_commit();
    }

    for (int r = 0; r < ROWS_PER_BLOCK; r++) {
        if (tid < 32) cp_wait<1>();          // row r complete
        __syncthreads();                      // publish row r; all done with row r-1
        if (tid < 32) {                       // prefetch row r+2 (overwrites buffer of r-1)
            if (r + 2 < ROWS_PER_BLOCK)
                cp_async16(&xbuf[(r + 2) % 3][tid * 4],
                           x + (base_row + r + 2) * II + tid * 4);
            cp_commit();
        }

        const float* xr = xbuf[r % 3] + ig * 16;
        float pn = 0.f, pd = 0.f;
#pragma unroll
        for (int ii = 0; ii < 16; ii++) {
            float xv  = xr[ii];
            float arg = fmaf(p[ii].x, xv, p[ii].y);
            float th  = tanh_fast(arg);
            pn = fmaf(p[ii].z, th, pn);
            pd = fmaf(p[ii].w, th, pd);
        }
        pn += __shfl_xor_sync(0xffffffffu, pn, 1);
        pn += __shfl_xor_sync(0xffffffffu, pn, 2);
        pn += __shfl_xor_sync(0xffffffffu, pn, 4);
        pd += __shfl_xor_sync(0xffffffffu, pd, 1);
        pd += __shfl_xor_sync(0xffffffffu, pd, 2);
        pd += __shfl_xor_sync(0xffffffffu, pd, 4);
        if (ig == 0) {
            float2 o = make_float2(pn + kn, pd + kd);
            __stcg(&g_wns[(base_row + r) * UU + u], o);
        }
    }
}

// ---------------- kernel 2: sequential scan + LayerNorm + FC head --------------------
// 512 blocks (one per batch), 256 threads: u = tid>>2, jg = tid&3 (16 j's each).
__global__ __launch_bounds__(256, 2) void scan_kernel(
    const float* __restrict__ outw, const float* __restrict__ outb,
    const float* __restrict__ lnw,  const float* __restrict__ lnb,
    const float* __restrict__ fcw,  const float* __restrict__ fcb,
    float* __restrict__ out)
{
    __shared__ float vbuf[2][UU];
    __shared__ float stats[2];

    const int tid = threadIdx.x;
    const int b   = blockIdx.x;
    const int u   = tid >> 2;
    const int jg  = tid & 3;

    float4 p[16];
#pragma unroll
    for (int jj = 0; jj < 16; jj++)
        p[jj] = g_rparam[(jg * 16 + jj) * UU + u];
    const float cmtu = g_cmt[u];
    const float nb   = g_numbase[u];
    const float db   = g_denbase[u];

    if (tid < UU) vbuf[0][tid] = 0.f;
    __syncthreads();

    const float2* __restrict__ wns = g_wns + (size_t)b * TT * UU;

    for (int t = 0; t < TT; t++) {
        float2 wnd = __ldcg(&wns[t * UU + u]);
#pragma unroll
        for (int k = 0; k < NUNF; k++) {
            const float* vr = vbuf[k & 1];
            float*       vw = vbuf[(k & 1) ^ 1];
            float pn = 0.f, pd = 0.f;
            const float* vrj = vr + jg * 16;
#pragma unroll
            for (int jj = 0; jj < 16; jj++) {
                float vj  = vrj[jj];
                float arg = fmaf(p[jj].x, vj, p[jj].y);
                float th  = tanh_fast(arg);
                pn = fmaf(p[jj].z, th, pn);
                pd = fmaf(p[jj].w, th, pd);
            }
            pn += __shfl_xor_sync(0xffffffffu, pn, 1);
            pn += __shfl_xor_sync(0xffffffffu, pn, 2);
            pd += __shfl_xor_sync(0xffffffffu, pd, 1);
            pd += __shfl_xor_sync(0xffffffffu, pd, 2);
            if (jg == 0) {
                float vu  = vr[u];
                float num = fmaf(cmtu, vu, nb) + wnd.x + pn;
                float den = db + wnd.y + pd;
                vw[u] = __fdividef(num, den);
            }
            __syncthreads();
        }
    }

    // ----- head: h = v*ow + ob; LayerNorm(eps=1e-5); out = h @ fc_w^T + fc_b -----
    __shared__ float hbuf[UU];
    if (tid < UU) hbuf[tid] = fmaf(vbuf[0][tid], outw[tid], outb[tid]);
    __syncthreads();
    if (tid < 32) {
        float a = hbuf[tid] + hbuf[tid + 32];
        float q = hbuf[tid] * hbuf[tid] + hbuf[tid + 32] * hbuf[tid + 32];
#pragma unroll
        for (int o = 16; o > 0; o >>= 1) {
            a += __shfl_down_sync(0xffffffffu, a, o);
            q += __shfl_down_sync(0xffffffffu, q, o);
        }
        if (tid == 0) {
            float mean = a * (1.0f / UU);
            float var  = q * (1.0f / UU) - mean * mean;
            stats[0] = mean;
            stats[1] = rsqrtf(var + 1e-5f);
        }
    }
    __syncthreads();
    if (tid < UU)
        hbuf[tid] = fmaf((hbuf[tid] - stats[0]) * stats[1], lnw[tid], lnb[tid]);
    __syncthreads();
    if (tid < OO) {
        float acc = fcb[tid];
#pragma unroll
        for (int uu = 0; uu < UU; uu++)
            acc = fmaf(hbuf[uu], fcw[tid * UU + uu], acc);
        out[b * OO + tid] = acc;
    }
}

// ---------------- launch --------------------------------------------------------------
extern "C" void kernel_launch(void* const* d_in, const int* in_sizes, int n_in,
                              void* d_out, int out_size)
{
    const float* x     = (const float*)d_in[0];
    const float* iw    = (const float*)d_in[1];
    const float* ibv   = (const float*)d_in[2];
    const float* sw    = (const float*)d_in[3];
    const float* smu   = (const float*)d_in[4];
    const float* ssig  = (const float*)d_in[5];
    const float* serev = (const float*)d_in[6];
    const float* w     = (const float*)d_in[7];
    const float* mu    = (const float*)d_in[8];
    const float* sig   = (const float*)d_in[9];
    const float* erev  = (const float*)d_in[10];
    const float* gleak = (const float*)d_in[11];
    const float* vleak = (const float*)d_in[12];
    const float* cm    = (const float*)d_in[13];
    const float* outw  = (const float*)d_in[14];
    const float* outb  = (const float*)d_in[15];
    const float* lnw   = (const float*)d_in[16];
    const float* lnb   = (const float*)d_in[17];
    const float* fcw   = (const float*)d_in[18];
    const float* fcb   = (const float*)d_in[19];
    float* out = (float*)d_out;

    precompute_kernel<<<1, 64>>>(iw, ibv, sw, smu, ssig, serev,
                                 w, mu, sig, erev, gleak, vleak, cm);

    int nblocks = (BB * TT) / ROWS_PER_BLOCK;   // 2048
    sensory_kernel<<<nblocks, 512>>>(x);

    scan_kernel<<<BB, 256>>>(outw, outb, lnw, lnb, fcw, fcb, out);
}

// round 2
// speedup vs baseline: 1.0841x; 1.0841x over previous
#include <cuda_runtime.h>
#include <cuda_bf16.h>
#include <cstdint>

// Problem constants (fixed by the dataset)
#define BB 512      // batch
#define TT 512      // timesteps
#define II 128      // sensory inputs
#define UU 64       // LTC units
#define OO 15       // outputs
#define NUNF 4      // ode unfolds
#define LTC_EPS 1e-8f

// ---------------- device scratch (allocation-free rule: __device__ globals) ---------
__device__ float4 g_sparam[II * UU];     // sensory per-synapse {a, b, ce, c}
__device__ float4 g_rparam[UU * UU];     // recurrent per-synapse {a, b, ce, c}
__device__ float  g_sKn[UU], g_sKd[UU];  // sensory constant sums
__device__ float  g_cmt[UU], g_numbase[UU], g_denbase[UU];
__device__ float2 g_wns[BB * TT * UU];   // (w_num_s, w_den_s) per (b,t,u)  ~134MB

// ---------------- helpers ------------------------------------------------------------
__device__ __forceinline__ float tanh_fast(float x) {
    float y;
    asm("tanh.approx.f32 %0, %1;" : "=f"(y) : "f"(x));
    return y;
}
__device__ __forceinline__ float softplus_f(float x) {
    return log1pf(expf(x));
}

// ---------------- kernel 0a: fold parameters (one thread per synapse) -----------------
// sigmoid(z) = 0.5*tanh(z/2) + 0.5
// sensory arg = 0.5*sigma*(x*iw + ib - mu)   -> a = 0.5*sigma*iw, b = 0.5*sigma*(ib - mu)
// s_act = sp(w)*sigmoid = c + c*th, c = 0.5*sp(w); num term uses ce = c*erev
__global__ void fold_params_kernel(
    const float* __restrict__ iw, const float* __restrict__ ib,
    const float* __restrict__ sw, const float* __restrict__ smu,
    const float* __restrict__ ssig, const float* __restrict__ serev,
    const float* __restrict__ w, const float* __restrict__ mu,
    const float* __restrict__ sig, const float* __restrict__ erev)
{
    int idx = blockIdx.x * blockDim.x + threadIdx.x;
    if (idx < II * UU) {
        int i = idx / UU;
        float c  = 0.5f * softplus_f(sw[idx]);
        float ce = c * serev[idx];
        float a  = 0.5f * ssig[idx] * iw[i];
        float b  = 0.5f * ssig[idx] * (ib[i] - smu[idx]);
        g_sparam[idx] = make_float4(a, b, ce, c);
    }
    int r = idx - II * UU;
    if (r >= 0 && r < UU * UU) {
        float c  = 0.5f * softplus_f(w[r]);
        float ce = c * erev[r];
        float a  = 0.5f * sig[r];
        float b  = -0.5f * sig[r] * mu[r];
        g_rparam[r] = make_float4(a, b, ce, c);
    }
}

// ---------------- kernel 0b: per-neuron constant sums ---------------------------------
__global__ void fold_neuron_kernel(
    const float* __restrict__ gleak, const float* __restrict__ vleak,
    const float* __restrict__ cm)
{
    int u = threadIdx.x;
    if (u >= UU) return;

    float kn = 0.f, kd = 0.f;
#pragma unroll 8
    for (int i = 0; i < II; i++) {
        float4 p = g_sparam[i * UU + u];
        kn += p.z; kd += p.w;
    }
    g_sKn[u] = kn;
    g_sKd[u] = kd;

    kn = 0.f; kd = 0.f;
#pragma unroll 8
    for (int j = 0; j < UU; j++) {
        float4 p = g_rparam[j * UU + u];
        kn += p.z; kd += p.w;
    }
    float gp  = softplus_f(gleak[u]);
    float cmt = (float)NUNF * softplus_f(cm[u]);   // sp(cm) / (1/UNFOLDS)
    g_cmt[u]     = cmt;
    g_numbase[u] = gp * vleak[u] + kn;
    g_denbase[u] = cmt + gp + kd + LTC_EPS;
}

// ---------------- kernel 1: sensory synapse sums over all (b,t) ----------------------
// Barrier-free: no smem. 512 threads: u = tid>>3, ig = tid&7 (8 groups of 16 inputs).
// Each warp loads the x row directly (LDG.128 x4 per thread; L1 hits after the first
// warp touches it). Warps run fully independently -> MUFU stays packed.
#define ROWS_PER_BLOCK 128
__global__ __launch_bounds__(512, 1) void sensory_kernel(const float* __restrict__ x)
{
    const int tid = threadIdx.x;
    const int u  = tid >> 3;
    const int ig = tid & 7;

    float4 p[16];
#pragma unroll
    for (int ii = 0; ii < 16; ii++)
        p[ii] = g_sparam[(ig * 16 + ii) * UU + u];
    const float kn = g_sKn[u];
    const float kd = g_sKd[u];

    const size_t base_row = (size_t)blockIdx.x * ROWS_PER_BLOCK;
    // thread's 16 x values start at column ig*16 -> 4 float4s
    const float4* __restrict__ xr = (const float4*)x + base_row * (II / 4) + ig * 4;

    float4 buf[2][4];
#pragma unroll
    for (int q = 0; q < 4; q++) buf[0][q] = xr[q];

#pragma unroll 2
    for (int r = 0; r < ROWS_PER_BLOCK; r++) {
        const int cb = r & 1;
        if (r + 1 < ROWS_PER_BLOCK) {
#pragma unroll
            for (int q = 0; q < 4; q++)
                buf[cb ^ 1][q] = xr[(r + 1) * (II / 4) + q];
        }

        float pn = 0.f, pd = 0.f;
#pragma unroll
        for (int q = 0; q < 4; q++) {
            float4 xv = buf[cb][q];
            const int base = q * 4;
            float t0 = tanh_fast(fmaf(p[base + 0].x, xv.x, p[base + 0].y));
            float t1 = tanh_fast(fmaf(p[base + 1].x, xv.y, p[base + 1].y));
            float t2 = tanh_fast(fmaf(p[base + 2].x, xv.z, p[base + 2].y));
            float t3 = tanh_fast(fmaf(p[base + 3].x, xv.w, p[base + 3].y));
            pn = fmaf(p[base + 0].z, t0, pn);  pd = fmaf(p[base + 0].w, t0, pd);
            pn = fmaf(p[base + 1].z, t1, pn);  pd = fmaf(p[base + 1].w, t1, pd);
            pn = fmaf(p[base + 2].z, t2, pn);  pd = fmaf(p[base + 2].w, t2, pd);
            pn = fmaf(p[base + 3].z, t3, pn);  pd = fmaf(p[base + 3].w, t3, pd);
        }
        pn += __shfl_xor_sync(0xffffffffu, pn, 1);
        pn += __shfl_xor_sync(0xffffffffu, pn, 2);
        pn += __shfl_xor_sync(0xffffffffu, pn, 4);
        pd += __shfl_xor_sync(0xffffffffu, pd, 1);
        pd += __shfl_xor_sync(0xffffffffu, pd, 2);
        pd += __shfl_xor_sync(0xffffffffu, pd, 4);
        if (ig == 0) {
            float2 o = make_float2(pn + kn, pd + kd);
            __stcg(&g_wns[(base_row + r) * UU + u], o);
        }
    }
}

// ---------------- kernel 2: sequential scan + LayerNorm + FC head --------------------
// 512 blocks (one per batch), 256 threads: u = tid>>2, jg = tid&3 (16 j's each).
// occ=3: three independent barrier domains per SM mutually hide the per-unfold tail.
__global__ __launch_bounds__(256, 3) void scan_kernel(
    const float* __restrict__ outw, const float* __restrict__ outb,
    const float* __restrict__ lnw,  const float* __restrict__ lnb,
    const float* __restrict__ fcw,  const float* __restrict__ fcb,
    float* __restrict__ out)
{
    __shared__ float4 vbuf4[2][UU / 4];
    __shared__ float  stats[2];
    __shared__ float  hbuf[UU];
    float* vbuf0 = (float*)vbuf4[0];
    float* vbuf1 = (float*)vbuf4[1];

    const int tid = threadIdx.x;
    const int b   = blockIdx.x;
    const int u   = tid >> 2;
    const int jg  = tid & 3;

    float4 p[16];
#pragma unroll
    for (int jj = 0; jj < 16; jj++)
        p[jj] = g_rparam[(jg * 16 + jj) * UU + u];
    const float cmtu = g_cmt[u];
    const float nb   = g_numbase[u];
    const float db   = g_denbase[u];

    if (tid < UU) vbuf0[tid] = 0.f;
    __syncthreads();

    const float2* __restrict__ wns = g_wns + (size_t)b * TT * UU;

    float2 wnd = __ldcg(&wns[u]);
    for (int t = 0; t < TT; t++) {
        float2 wnd_n = (t + 1 < TT) ? __ldcg(&wns[(t + 1) * UU + u])
                                    : make_float2(0.f, 0.f);
#pragma unroll
        for (int k = 0; k < NUNF; k++) {
            const float4* vr4 = vbuf4[k & 1] + jg * 4;
            const float*  vr  = (k & 1) ? vbuf1 : vbuf0;
            float*        vw  = (k & 1) ? vbuf0 : vbuf1;
            float pn = 0.f, pd = 0.f;
#pragma unroll
            for (int q = 0; q < 4; q++) {
                float4 v4 = vr4[q];
                const int base = q * 4;
                float t0 = tanh_fast(fmaf(p[base + 0].x, v4.x, p[base + 0].y));
                float t1 = tanh_fast(fmaf(p[base + 1].x, v4.y, p[base + 1].y));
                float t2 = tanh_fast(fmaf(p[base + 2].x, v4.z, p[base + 2].y));
                float t3 = tanh_fast(fmaf(p[base + 3].x, v4.w, p[base + 3].y));
                pn = fmaf(p[base + 0].z, t0, pn);  pd = fmaf(p[base + 0].w, t0, pd);
                pn = fmaf(p[base + 1].z, t1, pn);  pd = fmaf(p[base + 1].w, t1, pd);
                pn = fmaf(p[base + 2].z, t2, pn);  pd = fmaf(p[base + 2].w, t2, pd);
                pn = fmaf(p[base + 3].z, t3, pn);  pd = fmaf(p[base + 3].w, t3, pd);
            }
            pn += __shfl_xor_sync(0xffffffffu, pn, 1);
            pn += __shfl_xor_sync(0xffffffffu, pn, 2);
            pd += __shfl_xor_sync(0xffffffffu, pd, 1);
            pd += __shfl_xor_sync(0xffffffffu, pd, 2);
            if (jg == 0) {
                float vu  = vr[u];
                float num = fmaf(cmtu, vu, nb) + wnd.x + pn;
                float den = db + wnd.y + pd;
                vw[u] = __fdividef(num, den);
            }
            __syncthreads();
        }
        wnd = wnd_n;
    }

    // ----- head: h = v*ow + ob; LayerNorm(eps=1e-5); out = h @ fc_w^T + fc_b -----
    // final v lives in vbuf0 (4 unfolds per t -> even parity)
    if (tid < UU) hbuf[tid] = fmaf(vbuf0[tid], outw[tid], outb[tid]);
    __syncthreads();
    if (tid < 32) {
        float a = hbuf[tid] + hbuf[tid + 32];
        float q = hbuf[tid] * hbuf[tid] + hbuf[tid + 32] * hbuf[tid + 32];
#pragma unroll
        for (int o = 16; o > 0; o >>= 1) {
            a += __shfl_down_sync(0xffffffffu, a, o);
            q += __shfl_down_sync(0xffffffffu, q, o);
        }
        if (tid == 0) {
            float mean = a * (1.0f / UU);
            float var  = q * (1.0f / UU) - mean * mean;
            stats[0] = mean;
            stats[1] = rsqrtf(var + 1e-5f);
        }
    }
    __syncthreads();
    if (tid < UU)
        hbuf[tid] = fmaf((hbuf[tid] - stats[0]) * stats[1], lnw[tid], lnb[tid]);
    __syncthreads();
    if (tid < OO) {
        float acc = fcb[tid];
#pragma unroll
        for (int uu = 0; uu < UU; uu++)
            acc = fmaf(hbuf[uu], fcw[tid * UU + uu], acc);
        out[b * OO + tid] = acc;
    }
}

// ---------------- launch --------------------------------------------------------------
extern "C" void kernel_launch(void* const* d_in, const int* in_sizes, int n_in,
                              void* d_out, int out_size)
{
    const float* x     = (const float*)d_in[0];
    const float* iw    = (const float*)d_in[1];
    const float* ibv   = (const float*)d_in[2];
    const float* sw    = (const float*)d_in[3];
    const float* smu   = (const float*)d_in[4];
    const float* ssig  = (const float*)d_in[5];
    const float* serev = (const float*)d_in[6];
    const float* w     = (const float*)d_in[7];
    const float* mu    = (const float*)d_in[8];
    const float* sig   = (const float*)d_in[9];
    const float* erev  = (const float*)d_in[10];
    const float* gleak = (const float*)d_in[11];
    const float* vleak = (const float*)d_in[12];
    const float* cm    = (const float*)d_in[13];
    const float* outw  = (const float*)d_in[14];
    const float* outb  = (const float*)d_in[15];
    const float* lnw   = (const float*)d_in[16];
    const float* lnb   = (const float*)d_in[17];
    const float* fcw   = (const float*)d_in[18];
    const float* fcb   = (const float*)d_in[19];
    float* out = (float*)d_out;

    const int n_syn = II * UU + UU * UU;           // 12288
    fold_params_kernel<<<(n_syn + 255) / 256, 256>>>(iw, ibv, sw, smu, ssig, serev,
                                                     w, mu, sig, erev);
    fold_neuron_kernel<<<1, 64>>>(gleak, vleak, cm);

    int nblocks = (BB * TT) / ROWS_PER_BLOCK;      // 2048
    sensory_kernel<<<nblocks, 512>>>(x);

    scan_kernel<<<BB, 256>>>(outw, outb, lnw, lnb, fcw, fcb, out);
}

// round 3
// speedup vs baseline: 1.3782x; 1.2713x over previous
#include <cuda_runtime.h>
#include <cuda_bf16.h>
#include <cstdint>

// Problem constants (fixed by the dataset)
#define BB 512      // batch
#define TT 512      // timesteps
#define II 128      // sensory inputs
#define UU 64       // LTC units
#define OO 15       // outputs
#define NUNF 4      // ode unfolds
#define LTC_EPS 1e-8f

// ---------------- device scratch (allocation-free rule: __device__ globals) ---------
__device__ float4 g_sparam[II * UU];     // sensory per-synapse {a, b, ce, c}
__device__ float4 g_rparam[UU * UU];     // recurrent per-synapse {a, b, ce, c}
__device__ float  g_sKn[UU], g_sKd[UU];  // sensory constant sums
__device__ float  g_cmt[UU], g_numbase[UU], g_denbase[UU];
__device__ float2 g_wns[BB * TT * UU];   // (w_num_s, w_den_s) per (b,t,u)  ~134MB

// ---------------- helpers ------------------------------------------------------------
__device__ __forceinline__ float tanh_fast(float x) {
    float y;
    asm("tanh.approx.f32 %0, %1;" : "=f"(y) : "f"(x));
    return y;
}
__device__ __forceinline__ float softplus_f(float x) {
    return log1pf(expf(x));
}

// ---------------- kernel 0a: fold parameters (one thread per synapse) -----------------
// sigmoid(z) = 0.5*tanh(z/2) + 0.5
// sensory arg = 0.5*sigma*(x*iw + ib - mu)   -> a = 0.5*sigma*iw, b = 0.5*sigma*(ib - mu)
// s_act = sp(w)*sigmoid = c + c*th, c = 0.5*sp(w); num term uses ce = c*erev
// NOTE: erev is exactly +-1, so c == fabsf(ce); runtime kernels only need {a,b,ce}.
__global__ void fold_params_kernel(
    const float* __restrict__ iw, const float* __restrict__ ib,
    const float* __restrict__ sw, const float* __restrict__ smu,
    const float* __restrict__ ssig, const float* __restrict__ serev,
    const float* __restrict__ w, const float* __restrict__ mu,
    const float* __restrict__ sig, const float* __restrict__ erev)
{
    int idx = blockIdx.x * blockDim.x + threadIdx.x;
    if (idx < II * UU) {
        int i = idx / UU;
        float c  = 0.5f * softplus_f(sw[idx]);
        float ce = c * serev[idx];
        float a  = 0.5f * ssig[idx] * iw[i];
        float b  = 0.5f * ssig[idx] * (ib[i] - smu[idx]);
        g_sparam[idx] = make_float4(a, b, ce, c);
    }
    int r = idx - II * UU;
    if (r >= 0 && r < UU * UU) {
        float c  = 0.5f * softplus_f(w[r]);
        float ce = c * erev[r];
        float a  = 0.5f * sig[r];
        float b  = -0.5f * sig[r] * mu[r];
        g_rparam[r] = make_float4(a, b, ce, c);
    }
}

// ---------------- kernel 0b: per-neuron constant sums ---------------------------------
__global__ void fold_neuron_kernel(
    const float* __restrict__ gleak, const float* __restrict__ vleak,
    const float* __restrict__ cm)
{
    int u = threadIdx.x;
    if (u >= UU) return;

    float kn = 0.f, kd = 0.f;
#pragma unroll 8
    for (int i = 0; i < II; i++) {
        float4 p = g_sparam[i * UU + u];
        kn += p.z; kd += p.w;
    }
    g_sKn[u] = kn;
    g_sKd[u] = kd;

    kn = 0.f; kd = 0.f;
#pragma unroll 8
    for (int j = 0; j < UU; j++) {
        float4 p = g_rparam[j * UU + u];
        kn += p.z; kd += p.w;
    }
    float gp  = softplus_f(gleak[u]);
    float cmt = (float)NUNF * softplus_f(cm[u]);   // sp(cm) / (1/UNFOLDS)
    g_cmt[u]     = cmt;
    g_numbase[u] = gp * vleak[u] + kn;
    g_denbase[u] = cmt + gp + kd + LTC_EPS;
}

// ---------------- kernel 1: sensory synapse sums over all (b,t) ----------------------
// Barrier-free, no smem. 512 threads: u = tid>>3, ig = tid&7 (8 groups of 16 inputs).
// Two rows per iteration -> 32 independent tanh between shuffle tails.
#define ROWS_PER_BLOCK 128
__global__ __launch_bounds__(512, 1) void sensory_kernel(const float* __restrict__ x)
{
    const int tid = threadIdx.x;
    const int u  = tid >> 3;
    const int ig = tid & 7;

    float pa[16], pb[16], pce[16];
#pragma unroll
    for (int ii = 0; ii < 16; ii++) {
        float4 p = g_sparam[(ig * 16 + ii) * UU + u];
        pa[ii] = p.x; pb[ii] = p.y; pce[ii] = p.z;
    }
    const float kn = g_sKn[u];
    const float kd = g_sKd[u];

    const size_t base_row = (size_t)blockIdx.x * ROWS_PER_BLOCK;
    // thread's 16 x values start at column ig*16 -> 4 float4s
    const float4* __restrict__ xr = (const float4*)x + base_row * (II / 4) + ig * 4;

    for (int r = 0; r < ROWS_PER_BLOCK; r += 2) {
        float4 x0[4], x1[4];
#pragma unroll
        for (int q = 0; q < 4; q++) {
            x0[q] = xr[(size_t)r * (II / 4) + q];
            x1[q] = xr[(size_t)(r + 1) * (II / 4) + q];
        }

        float pn0 = 0.f, pd0 = 0.f, pn1 = 0.f, pd1 = 0.f;
#pragma unroll
        for (int q = 0; q < 4; q++) {
            const int s = q * 4;
            const float xv0[4] = {x0[q].x, x0[q].y, x0[q].z, x0[q].w};
            const float xv1[4] = {x1[q].x, x1[q].y, x1[q].z, x1[q].w};
#pragma unroll
            for (int e = 0; e < 4; e++) {
                float t0 = tanh_fast(fmaf(pa[s + e], xv0[e], pb[s + e]));
                float t1 = tanh_fast(fmaf(pa[s + e], xv1[e], pb[s + e]));
                float ce = pce[s + e];
                float c  = fabsf(ce);
                pn0 = fmaf(ce, t0, pn0);  pd0 = fmaf(c, t0, pd0);
                pn1 = fmaf(ce, t1, pn1);  pd1 = fmaf(c, t1, pd1);
            }
        }
#pragma unroll
        for (int o = 1; o <= 4; o <<= 1) {
            pn0 += __shfl_xor_sync(0xffffffffu, pn0, o);
            pn1 += __shfl_xor_sync(0xffffffffu, pn1, o);
            pd0 += __shfl_xor_sync(0xffffffffu, pd0, o);
            pd1 += __shfl_xor_sync(0xffffffffu, pd1, o);
        }
        if (ig == 0) {
            __stcg(&g_wns[(base_row + r) * UU + u],     make_float2(pn0 + kn, pd0 + kd));
            __stcg(&g_wns[(base_row + r + 1) * UU + u], make_float2(pn1 + kn, pd1 + kd));
        }
    }
}

// ---------------- kernel 2: sequential scan + LayerNorm + FC head --------------------
// One block (64 threads = 2 warps) per batch. Thread u owns unit u completely:
// all 64 recurrent synapse params in registers, local accumulation, local division.
// Only cross-thread traffic: v broadcast via 64-float smem + one 2-warp barrier/unfold.
__global__ __launch_bounds__(64, 4) void scan_kernel(
    const float* __restrict__ outw, const float* __restrict__ outb,
    const float* __restrict__ lnw,  const float* __restrict__ lnb,
    const float* __restrict__ fcw,  const float* __restrict__ fcb,
    float* __restrict__ out)
{
    __shared__ float4 vsm4[2][UU / 4];
    __shared__ float  stats[2];
    __shared__ float  hbuf[UU];

    const int u = threadIdx.x;        // 0..63 : unit owned by this thread
    const int b = blockIdx.x;

    float ra[UU], rb[UU], rce[UU];
#pragma unroll
    for (int j = 0; j < UU; j++) {
        float4 p = g_rparam[j * UU + u];
        ra[j] = p.x; rb[j] = p.y; rce[j] = p.z;
    }
    const float cmtu = g_cmt[u];
    const float nb   = g_numbase[u];
    const float db   = g_denbase[u];

    ((float*)vsm4[0])[u] = 0.f;
    float vu = 0.f;
    __syncthreads();

    const float2* __restrict__ wns = g_wns + (size_t)b * TT * UU;
    float2 wnd = __ldcg(&wns[u]);

    for (int t = 0; t < TT; t++) {
        float2 wnd_n = (t + 1 < TT) ? __ldcg(&wns[(t + 1) * UU + u])
                                    : make_float2(0.f, 0.f);
#pragma unroll
        for (int k = 0; k < NUNF; k++) {
            const float4* vr4 = vsm4[k & 1];
            float pn = 0.f, pd = 0.f;
#pragma unroll
            for (int q = 0; q < UU / 4; q++) {
                float4 v4 = vr4[q];
                const int s = q * 4;
                float t0 = tanh_fast(fmaf(ra[s + 0], v4.x, rb[s + 0]));
                float t1 = tanh_fast(fmaf(ra[s + 1], v4.y, rb[s + 1]));
                float t2 = tanh_fast(fmaf(ra[s + 2], v4.z, rb[s + 2]));
                float t3 = tanh_fast(fmaf(ra[s + 3], v4.w, rb[s + 3]));
                pn = fmaf(rce[s + 0], t0, pn);  pd = fmaf(fabsf(rce[s + 0]), t0, pd);
                pn = fmaf(rce[s + 1], t1, pn);  pd = fmaf(fabsf(rce[s + 1]), t1, pd);
                pn = fmaf(rce[s + 2], t2, pn);  pd = fmaf(fabsf(rce[s + 2]), t2, pd);
                pn = fmaf(rce[s + 3], t3, pn);  pd = fmaf(fabsf(rce[s + 3]), t3, pd);
            }
            float num = fmaf(cmtu, vu, nb) + wnd.x + pn;
            float den = db + wnd.y + pd;
            vu = __fdividef(num, den);
            ((float*)vsm4[(k & 1) ^ 1])[u] = vu;
            __syncthreads();
        }
        wnd = wnd_n;
    }

    // ----- head: h = v*ow + ob; LayerNorm(eps=1e-5); out = h @ fc_w^T + fc_b -----
    float h = fmaf(vu, outw[u], outb[u]);
    hbuf[u] = h;
    __syncthreads();
    if (u < 32) {
        float a = hbuf[u] + hbuf[u + 32];
        float q = hbuf[u] * hbuf[u] + hbuf[u + 32] * hbuf[u + 32];
#pragma unroll
        for (int o = 16; o > 0; o >>= 1) {
            a += __shfl_down_sync(0xffffffffu, a, o);
            q += __shfl_down_sync(0xffffffffu, q, o);
        }
        if (u == 0) {
            float mean = a * (1.0f / UU);
            float var  = q * (1.0f / UU) - mean * mean;
            stats[0] = mean;
            stats[1] = rsqrtf(var + 1e-5f);
        }
    }
    __syncthreads();
    hbuf[u] = fmaf((h - stats[0]) * stats[1], lnw[u], lnb[u]);
    __syncthreads();
    if (u < OO) {
        float acc = fcb[u];
#pragma unroll
        for (int uu = 0; uu < UU; uu++)
            acc = fmaf(hbuf[uu], fcw[u * UU + uu], acc);
        out[b * OO + u] = acc;
    }
}

// ---------------- launch --------------------------------------------------------------
extern "C" void kernel_launch(void* const* d_in, const int* in_sizes, int n_in,
                              void* d_out, int out_size)
{
    const float* x     = (const float*)d_in[0];
    const float* iw    = (const float*)d_in[1];
    const float* ibv   = (const float*)d_in[2];
    const float* sw    = (const float*)d_in[3];
    const float* smu   = (const float*)d_in[4];
    const float* ssig  = (const float*)d_in[5];
    const float* serev = (const float*)d_in[6];
    const float* w     = (const float*)d_in[7];
    const float* mu    = (const float*)d_in[8];
    const float* sig   = (const float*)d_in[9];
    const float* erev  = (const float*)d_in[10];
    const float* gleak = (const float*)d_in[11];
    const float* vleak = (const float*)d_in[12];
    const float* cm    = (const float*)d_in[13];
    const float* outw  = (const float*)d_in[14];
    const float* outb  = (const float*)d_in[15];
    const float* lnw   = (const float*)d_in[16];
    const float* lnb   = (const float*)d_in[17];
    const float* fcw   = (const float*)d_in[18];
    const float* fcb   = (const float*)d_in[19];
    float* out = (float*)d_out;

    const int n_syn = II * UU + UU * UU;           // 12288
    fold_params_kernel<<<(n_syn + 255) / 256, 256>>>(iw, ibv, sw, smu, ssig, serev,
                                                     w, mu, sig, erev);
    fold_neuron_kernel<<<1, 64>>>(gleak, vleak, cm);

    int nblocks = (BB * TT) / ROWS_PER_BLOCK;      // 2048
    sensory_kernel<<<nblocks, 512>>>(x);

    scan_kernel<<<BB, 64>>>(outw, outb, lnw, lnb, fcw, fcb, out);
}